// round 15
// baseline (speedup 1.0000x reference)
#include <cuda_runtime.h>

// SplineLoss on GB300 — FINAL (champion = R12, 6.624us measured).
//
// Reference samples the spline only at integer knot times
// (t = 0,10,...,1020) where dx == 0.0 exactly, so every moment-dependent
// term vanishes and the loss reduces EXACTLY to a strided MSE:
//   loss == mean over s,b,d of (true[b,10s,d] - pred[b,10s,d])^2
//
// Measured-optimal configuration after a 14-round search:
//  - 824 blocks x 256 thr, one float4-pair per thread, single wave
//    (beats 103/206/412/1648-block and 128/512-thread variants)
//  - SHFL reduction trees (beat redux.sync by ~0.25us on sm_103)
//  - two-level deterministic fixed-point atomic tail: 8 bins on separate
//    256B lines (103 ops/address), bin-last forwards exact total, final
//    fold writes the mean. All-integer adds -> bit-exact (rel_err 0.0).
//  - epilogue reorder: fold ATOMG (318cy RT, critical) issued before the
//    bin-reset STG so the store lands in its shadow.
// Residual time = ~4.3us kernel-independent launch/drain at replay clock
// + compulsory 6.76MB traffic; no on-chip pipe above 14%.

#define T_ 1024
#define D4_ 16                   // 64 floats per row = 16 float4
#define S_ 103                   // sample times 0,10,...,1020
#define ROW_STRIDE4_ (T_ * D4_)  // float4 stride between batches
#define COUNT_ 843776.0          // 128 * 103 * 64
#define FIX_SCALE 16777216.0     // 2^24

constexpr int NBLK  = 8 * S_;    // 824 blocks, 8 per sample time
constexpr int NTHR  = 256;       // 16 batches x 16 float4
constexpr int NBINS = 8;
constexpr int BINSZ = NBLK / NBINS;   // 103

__device__ __align__(256) unsigned long long g_bins[NBINS * 32]; // use [i*32]
__device__ __align__(256) unsigned long long g_final = 0;

__global__ __launch_bounds__(NTHR) void spline_mse_final(
    const float* __restrict__ yt, const float* __restrict__ yp,
    float* __restrict__ out)
{
    const int s = blockIdx.x >> 3;             // 0..102
    const int q = blockIdx.x & 7;              // batch group [16q, 16q+16)
    const int d4   = threadIdx.x & (D4_ - 1);
    const int brel = threadIdx.x >> 4;         // 0..15

    const int addr = s * 10 * D4_ + (q * 16 + brel) * ROW_STRIDE4_ + d4;
    const float4 va = __ldg((const float4*)yt + addr);
    const float4 vb = __ldg((const float4*)yp + addr);

    float e0 = va.x - vb.x;
    float e1 = va.y - vb.y;
    float e2 = va.z - vb.z;
    float e3 = va.w - vb.w;
    float acc = e0 * e0;
    acc = fmaf(e1, e1, acc);
    acc = fmaf(e2, e2, acc);
    acc = fmaf(e3, e3, acc);

    // block reduce (fixed order -> deterministic)
    #pragma unroll
    for (int o = 16; o > 0; o >>= 1)
        acc += __shfl_down_sync(0xffffffffu, acc, o);

    __shared__ float sh[NTHR / 32];
    if ((threadIdx.x & 31) == 0) sh[threadIdx.x >> 5] = acc;
    __syncthreads();

    if (threadIdx.x != 0) return;              // thread 0 only past here

    float v = sh[0];
    #pragma unroll
    for (int w = 1; w < NTHR / 32; w++) v += sh[w];

    // level 1: bin atomic (103 blocks per address, 8 addresses in parallel)
    unsigned long long fixed =
        __double2ull_rn((double)v * FIX_SCALE);          // v >= 0, exact int
    unsigned long long* bin = &g_bins[(blockIdx.x & (NBINS - 1)) * 32];
    unsigned long long old = atomicAdd(bin, (fixed << 16) | 1ull);

    if ((old & 0xFFFFull) != (unsigned long long)(BINSZ - 1)) return;

    // bin-last: fold FIRST (critical ATOMG), then reset bin in its shadow
    unsigned long long bin_total = (old >> 16) + fixed;
    unsigned long long fold = atomicAdd(&g_final, (bin_total << 16) | 1ull);
    *bin = 0ull;                                         // next-replay reset

    if ((fold & 0xFFFFull) == (unsigned long long)(NBINS - 1)) {
        unsigned long long total = (fold >> 16) + bin_total;
        out[0] = (float)((double)total / (FIX_SCALE * COUNT_));
        g_final = 0ull;                                  // reset for replay
    }
}

extern "C" void kernel_launch(void* const* d_in, const int* in_sizes, int n_in,
                              void* d_out, int out_size)
{
    const float* yt = (const float*)d_in[0];   // true_frames
    const float* yp = (const float*)d_in[1];   // predicted_frames
    spline_mse_final<<<NBLK, NTHR>>>(yt, yp, (float*)d_out);
}

// round 16
// speedup vs baseline: 1.0385x; 1.0385x over previous
#include <cuda_runtime.h>

// SplineLoss on GB300 — FINAL champion (R12 structure; best measured 6.624us,
// run-to-run noise band +/-0.3us established in R15).
//
// Reference samples the spline only at integer knot times
// (t = 0,10,...,1020) where dx == 0.0 exactly, so every moment-dependent
// term vanishes and the loss reduces EXACTLY to a strided MSE:
//   loss == mean over s,b,d of (true[b,10s,d] - pred[b,10s,d])^2
//
// Measured-optimal configuration over a 15-round search:
//  - 824 blocks x 256 thr, one float4-pair per thread, single wave
//    (beats 103/206/412/1648-block and 128/512-thread variants)
//  - SHFL reduction trees (beat redux.sync.u32 on sm_103)
//  - two-level deterministic fixed-point atomic tail: 8 bins on separate
//    256B lines (103 ops/address), bin-last forwards exact total, final
//    fold writes the mean. All-integer adds -> bit-exact (rel_err 0.0).
//  - epilogue: fold ATOMG issued before the bin-reset STG (store in shadow).
// Residual time = ~4.3us kernel-independent launch/drain at replay clock
// + compulsory 6.76MB traffic; no on-chip pipe above 14%. Structural
// alternatives within the noise band; nothing with predicted effect
// above it remains.

#define T_ 1024
#define D4_ 16                   // 64 floats per row = 16 float4
#define S_ 103                   // sample times 0,10,...,1020
#define ROW_STRIDE4_ (T_ * D4_)  // float4 stride between batches
#define COUNT_ 843776.0          // 128 * 103 * 64
#define FIX_SCALE 16777216.0     // 2^24

constexpr int NBLK  = 8 * S_;    // 824 blocks, 8 per sample time
constexpr int NTHR  = 256;       // 16 batches x 16 float4
constexpr int NBINS = 8;
constexpr int BINSZ = NBLK / NBINS;   // 103

__device__ __align__(256) unsigned long long g_bins[NBINS * 32]; // use [i*32]
__device__ __align__(256) unsigned long long g_final = 0;

__global__ __launch_bounds__(NTHR) void spline_mse_champion(
    const float* __restrict__ yt, const float* __restrict__ yp,
    float* __restrict__ out)
{
    const int s = blockIdx.x >> 3;             // 0..102
    const int q = blockIdx.x & 7;              // batch group [16q, 16q+16)
    const int d4   = threadIdx.x & (D4_ - 1);
    const int brel = threadIdx.x >> 4;         // 0..15

    const int addr = s * 10 * D4_ + (q * 16 + brel) * ROW_STRIDE4_ + d4;
    const float4 va = __ldg((const float4*)yt + addr);
    const float4 vb = __ldg((const float4*)yp + addr);

    float e0 = va.x - vb.x;
    float e1 = va.y - vb.y;
    float e2 = va.z - vb.z;
    float e3 = va.w - vb.w;
    float acc = e0 * e0;
    acc = fmaf(e1, e1, acc);
    acc = fmaf(e2, e2, acc);
    acc = fmaf(e3, e3, acc);

    // block reduce (fixed order -> deterministic)
    #pragma unroll
    for (int o = 16; o > 0; o >>= 1)
        acc += __shfl_down_sync(0xffffffffu, acc, o);

    __shared__ float sh[NTHR / 32];
    if ((threadIdx.x & 31) == 0) sh[threadIdx.x >> 5] = acc;
    __syncthreads();

    if (threadIdx.x != 0) return;              // thread 0 only past here

    float v = sh[0];
    #pragma unroll
    for (int w = 1; w < NTHR / 32; w++) v += sh[w];

    // level 1: bin atomic (103 blocks per address, 8 addresses in parallel)
    unsigned long long fixed =
        __double2ull_rn((double)v * FIX_SCALE);          // v >= 0, exact int
    unsigned long long* bin = &g_bins[(blockIdx.x & (NBINS - 1)) * 32];
    unsigned long long old = atomicAdd(bin, (fixed << 16) | 1ull);

    if ((old & 0xFFFFull) != (unsigned long long)(BINSZ - 1)) return;

    // bin-last: fold FIRST (critical ATOMG), then reset bin in its shadow
    unsigned long long bin_total = (old >> 16) + fixed;
    unsigned long long fold = atomicAdd(&g_final, (bin_total << 16) | 1ull);
    *bin = 0ull;                                         // next-replay reset

    if ((fold & 0xFFFFull) == (unsigned long long)(NBINS - 1)) {
        unsigned long long total = (fold >> 16) + bin_total;
        out[0] = (float)((double)total / (FIX_SCALE * COUNT_));
        g_final = 0ull;                                  // reset for replay
    }
}

extern "C" void kernel_launch(void* const* d_in, const int* in_sizes, int n_in,
                              void* d_out, int out_size)
{
    const float* yt = (const float*)d_in[0];   // true_frames
    const float* yp = (const float*)d_in[1];   // predicted_frames
    spline_mse_champion<<<NBLK, NTHR>>>(yt, yp, (float*)d_out);
}